// round 5
// baseline (speedup 1.0000x reference)
#include <cuda_runtime.h>
#include <cuda_bf16.h>

// x: [32, 512, 512, 3] f32  -> out: [32, 128, 128, 3] f32
// 13-tap separable gaussian (sigma=1.5), zero padding, out = blur[4i, 4j]
//
// Phase 1 (vertical): scatter-accumulate, 5-deep LDG.128 prefetch ring.
// Phase 2 (horizontal): planar smem, 4 conflict-free LDS.128 + 13 FFMA-imm.
// NROWS=4 tiles, 1024 CTAs, 3 CTAs/SM (reg-capped) -> small tail, high occ.

#define ROWF4   384            // float4 per input image row (512*3/4)
#define PROW    528            // floats per padded plane row (8 + 512 + 8)
#define NROWS   4              // output rows per tile
#define PPLANE  (NROWS * PROW) // floats per plane                 = 2112
#define SMEM_BYTES (3 * PPLANE * 4)   // 25344 B -> 3 CTAs/SM uses 76 KB

#define NIN     (4 * NROWS + 9)   // input rows touched per tile   = 25
#define PF      5                 // prefetch ring depth

__device__ __forceinline__ float4 f4zero() { return make_float4(0.f, 0.f, 0.f, 0.f); }

__global__ __launch_bounds__(384, 3)
void aa_fused(const float4* __restrict__ x4, float* __restrict__ out)
{
    extern __shared__ float sm[];

    const int t  = threadIdx.x;          // 0..383 : one float4 column of a row
    const int n  = blockIdx.y;           // image
    const int i0 = blockIdx.x * NROWS;   // first output row of tile

    // normalized 1-D gaussian (sigma = 1.5) as literals -> FFMA-imm
    const float Wt[13] = {
        0.00008922f, 0.00102822f, 0.00759740f, 0.03599436f,
        0.10934121f, 0.21296756f, 0.26596430f, 0.21296756f,
        0.10934121f, 0.03599436f, 0.00759740f, 0.00102822f,
        0.00008922f
    };

    // Zero horizontal padding: 3 planes * 4 rows * 16 pad floats = 192 stores
    if (t < 3 * NROWS * 16) {
        int plane = t >> 6;              // t / 64
        int rem   = t & 63;
        int row   = rem >> 4;
        int o     = rem & 15;
        sm[plane * PPLANE + row * PROW + (o < 8 ? o : 512 + o)] = 0.f;
    }

    // Planar scatter bases: thread t owns interleaved floats 4t..4t+3.
    int sbase[4];
    #pragma unroll
    for (int m = 0; m < 4; ++m) {
        int f    = 4 * t + m;
        int col  = f / 3;
        int chan = f - 3 * col;
        sbase[m] = chan * PPLANE + 8 + col;
    }

    // ---------------- Phase 1: vertical blur (scatter-accumulate) ----------------
    const float4* xcol = x4 + (size_t)n * (512 * ROWF4) + t;
    const int R0 = 4 * i0 - 6;                    // first input row (may be <0)

    float4 buf[PF];
    #pragma unroll
    for (int s = 0; s < PF; ++s) {
        int r = R0 + s;
        buf[s] = (r >= 0) ? __ldg(xcol + r * ROWF4) : f4zero();
    }

    float4 acc[NROWS];
    #pragma unroll
    for (int ii = 0; ii < NROWS; ++ii) acc[ii] = f4zero();

    #pragma unroll
    for (int s = 0; s < NIN; ++s) {
        const float4 v = buf[s % PF];

        if (s + PF < NIN) {                       // refill ring
            int r = R0 + s + PF;                  // can be -1 at top tile (PF=5)
            buf[s % PF] = (r >= 0 && r < 512) ? __ldg(xcol + r * ROWF4) : f4zero();
        }

        const int p = s & 3;
        #pragma unroll
        for (int k = p; k <= 12; k += 4) {        // taps congruent to s mod 4
            const int ii = (s - k) >> 2;
            if (ii >= 0 && ii < NROWS) {
                const float wk = Wt[k];
                acc[ii].x = fmaf(wk, v.x, acc[ii].x);
                acc[ii].y = fmaf(wk, v.y, acc[ii].y);
                acc[ii].z = fmaf(wk, v.z, acc[ii].z);
                acc[ii].w = fmaf(wk, v.w, acc[ii].w);
            }
        }
    }

    // Store blurred rows: planar scatter, 4 STS.32 per row
    #pragma unroll
    for (int ii = 0; ii < NROWS; ++ii) {
        const int ro = ii * PROW;
        sm[sbase[0] + ro] = acc[ii].x;
        sm[sbase[1] + ro] = acc[ii].y;
        sm[sbase[2] + ro] = acc[ii].z;
        sm[sbase[3] + ro] = acc[ii].w;
    }

    __syncthreads();

    // ---------------- Phase 2: horizontal blur ----------------
    // c = t>>7 (warp-uniform plane), j = t&127 (consecutive lanes)
    const int j = t & 127;
    const int c = t >> 7;

    const float4* sp4 = reinterpret_cast<const float4*>(sm) + (c * PPLANE) / 4 + j;
    float* opix = out + ((size_t)(n * 128 + i0) * 128 + j) * 3 + c;

    #pragma unroll
    for (int rr = 0; rr < NROWS; ++rr) {
        float4 a = sp4[rr * (PROW / 4) + 0];
        float4 b = sp4[rr * (PROW / 4) + 1];
        float4 d = sp4[rr * (PROW / 4) + 2];
        float4 e = sp4[rr * (PROW / 4) + 3];
        // s[0..15] = cols 4j-8 .. 4j+7 ; taps at s[2..14]
        float acch;
        acch = Wt[0] * a.z;
        acch = fmaf(Wt[1],  a.w, acch);
        acch = fmaf(Wt[2],  b.x, acch);
        acch = fmaf(Wt[3],  b.y, acch);
        acch = fmaf(Wt[4],  b.z, acch);
        acch = fmaf(Wt[5],  b.w, acch);
        acch = fmaf(Wt[6],  d.x, acch);
        acch = fmaf(Wt[7],  d.y, acch);
        acch = fmaf(Wt[8],  d.z, acch);
        acch = fmaf(Wt[9],  d.w, acch);
        acch = fmaf(Wt[10], e.x, acch);
        acch = fmaf(Wt[11], e.y, acch);
        acch = fmaf(Wt[12], e.z, acch);
        opix[rr * 384] = acch;
    }
}

extern "C" void kernel_launch(void* const* d_in, const int* in_sizes, int n_in,
                              void* d_out, int out_size)
{
    (void)in_sizes; (void)n_in; (void)out_size;
    const float4* x4  = (const float4*)d_in[0];
    float*        out = (float*)d_out;

    cudaFuncSetAttribute(aa_fused, cudaFuncAttributeMaxDynamicSharedMemorySize, SMEM_BYTES);

    dim3 grid(32, 32);      // 32 row-tiles of 4 output rows x 32 images = 1024 CTAs
    aa_fused<<<grid, 384, SMEM_BYTES>>>(x4, out);
}

// round 6
// speedup vs baseline: 1.0270x; 1.0270x over previous
#include <cuda_runtime.h>
#include <cuda_bf16.h>

// x: [32, 512, 512, 3] f32  -> out: [32, 128, 128, 3] f32
// 13-tap separable gaussian (sigma=1.5), zero padding, out = blur[4i, 4j]
//
// Phase 1 (vertical): streaming scatter-accumulate with a ROLLING 4-slot
//   accumulator window (slot = ii & 3). Output row ii completes at input
//   step s = 4*ii+12, is flushed to planar smem, slot recycled for ii+4.
//   -> accumulator regs independent of tile height: NROWS=8 at ~52 regs.
// Phase 2 (horizontal): planar smem, 4 conflict-free LDS.128 + 13 FFMA-imm.
// NROWS=8, 512 CTAs, 3 CTAs/SM -> 1.15 waves, halo 1.14x, occ ~51%.

#define ROWF4   384            // float4 per input image row (512*3/4)
#define PROW    528            // floats per padded plane row (8 + 512 + 8)
#define NROWS   8              // output rows per tile
#define PPLANE  (NROWS * PROW) // floats per plane                 = 4224
#define SMEM_BYTES (3 * PPLANE * 4)   // 50688 B -> 3 CTAs/SM = 152 KB

#define NIN     (4 * NROWS + 9)   // input rows touched per tile   = 41
#define PF      4                 // prefetch ring depth

__device__ __forceinline__ float4 f4zero() { return make_float4(0.f, 0.f, 0.f, 0.f); }

__global__ __launch_bounds__(384, 3)
void aa_fused(const float4* __restrict__ x4, float* __restrict__ out)
{
    extern __shared__ float sm[];

    const int t  = threadIdx.x;          // 0..383 : one float4 column of a row
    const int n  = blockIdx.y;           // image
    const int i0 = blockIdx.x * NROWS;   // first output row of tile

    // normalized 1-D gaussian (sigma = 1.5) as literals -> FFMA-imm
    const float Wt[13] = {
        0.00008922f, 0.00102822f, 0.00759740f, 0.03599436f,
        0.10934121f, 0.21296756f, 0.26596430f, 0.21296756f,
        0.10934121f, 0.03599436f, 0.00759740f, 0.00102822f,
        0.00008922f
    };

    // Zero horizontal padding: 3 planes * 8 rows * 16 pad floats = 384 = blockDim
    {
        int plane = t >> 7;
        int rem   = t & 127;
        int row   = rem >> 4;
        int o     = rem & 15;
        sm[plane * PPLANE + row * PROW + (o < 8 ? o : 512 + o)] = 0.f;
    }

    // Planar scatter bases: thread t owns interleaved floats 4t..4t+3.
    int sbase[4];
    #pragma unroll
    for (int m = 0; m < 4; ++m) {
        int f    = 4 * t + m;
        int col  = f / 3;
        int chan = f - 3 * col;
        sbase[m] = chan * PPLANE + 8 + col;
    }

    // ---------------- Phase 1: vertical blur (streaming scatter-accumulate) ----
    const float4* xcol = x4 + (size_t)n * (512 * ROWF4) + t;
    const int R0 = 4 * i0 - 6;                    // first input row (may be <0)

    float4 buf[PF];
    #pragma unroll
    for (int s = 0; s < PF; ++s) {                // rows R0 .. R0+3 (max 477 < 512)
        int r = R0 + s;
        buf[s] = (r >= 0) ? __ldg(xcol + r * ROWF4) : f4zero();
    }

    float4 acc[4];
    #pragma unroll
    for (int q = 0; q < 4; ++q) acc[q] = f4zero();

    #pragma unroll
    for (int s = 0; s < NIN; ++s) {
        const float4 v = buf[s & 3];              // PF == 4

        if (s + PF < NIN) {                       // refill ring
            int r = R0 + s + PF;                  // may be <0 (top) or >511 (bottom)
            buf[s & 3] = (r >= 0 && r < 512) ? __ldg(xcol + r * ROWF4) : f4zero();
        }

        const int p = s & 3;
        #pragma unroll
        for (int k = p; k <= 12; k += 4) {        // taps congruent to s mod 4
            const int ii = (s - k) >> 2;
            if (ii >= 0 && ii < NROWS) {
                const int   sl = ii & 3;
                const float wk = Wt[k];
                acc[sl].x = fmaf(wk, v.x, acc[sl].x);
                acc[sl].y = fmaf(wk, v.y, acc[sl].y);
                acc[sl].z = fmaf(wk, v.z, acc[sl].z);
                acc[sl].w = fmaf(wk, v.w, acc[sl].w);
            }
        }

        // output row ii = (s-12)/4 completes at s = 4*ii + 12 -> flush + recycle
        if (s >= 12 && ((s - 12) & 3) == 0) {
            const int ii = (s - 12) >> 2;
            const int sl = ii & 3;
            const int ro = ii * PROW;
            sm[sbase[0] + ro] = acc[sl].x;
            sm[sbase[1] + ro] = acc[sl].y;
            sm[sbase[2] + ro] = acc[sl].z;
            sm[sbase[3] + ro] = acc[sl].w;
            acc[sl] = f4zero();
        }
    }

    __syncthreads();

    // ---------------- Phase 2: horizontal blur ----------------
    // c = t>>7 (warp-uniform plane), j = t&127 (consecutive lanes)
    const int j = t & 127;
    const int c = t >> 7;

    const float4* sp4 = reinterpret_cast<const float4*>(sm) + (c * PPLANE) / 4 + j;
    float* opix = out + ((size_t)(n * 128 + i0) * 128 + j) * 3 + c;

    #pragma unroll
    for (int rr = 0; rr < NROWS; ++rr) {
        float4 a = sp4[rr * (PROW / 4) + 0];
        float4 b = sp4[rr * (PROW / 4) + 1];
        float4 d = sp4[rr * (PROW / 4) + 2];
        float4 e = sp4[rr * (PROW / 4) + 3];
        // s[0..15] = cols 4j-8 .. 4j+7 ; taps at s[2..14]
        float acch;
        acch = Wt[0] * a.z;
        acch = fmaf(Wt[1],  a.w, acch);
        acch = fmaf(Wt[2],  b.x, acch);
        acch = fmaf(Wt[3],  b.y, acch);
        acch = fmaf(Wt[4],  b.z, acch);
        acch = fmaf(Wt[5],  b.w, acch);
        acch = fmaf(Wt[6],  d.x, acch);
        acch = fmaf(Wt[7],  d.y, acch);
        acch = fmaf(Wt[8],  d.z, acch);
        acch = fmaf(Wt[9],  d.w, acch);
        acch = fmaf(Wt[10], e.x, acch);
        acch = fmaf(Wt[11], e.y, acch);
        acch = fmaf(Wt[12], e.z, acch);
        opix[rr * 384] = acch;
    }
}

extern "C" void kernel_launch(void* const* d_in, const int* in_sizes, int n_in,
                              void* d_out, int out_size)
{
    (void)in_sizes; (void)n_in; (void)out_size;
    const float4* x4  = (const float4*)d_in[0];
    float*        out = (float*)d_out;

    cudaFuncSetAttribute(aa_fused, cudaFuncAttributeMaxDynamicSharedMemorySize, SMEM_BYTES);

    dim3 grid(16, 32);      // 16 row-tiles of 8 output rows x 32 images = 512 CTAs
    aa_fused<<<grid, 384, SMEM_BYTES>>>(x4, out);
}